// round 17
// baseline (speedup 1.0000x reference)
#include <cuda_runtime.h>
#include <cuda_bf16.h>
#include <math.h>
#include <stdint.h>

#define NN 50000
#define NE 400000
#define DD 128
#define NG 512

#define BSTR 40           // bf16 smem stride (80B rows: ldmatrix conflict-free, 16B aligned)

// ---------------- device scratch ----------------
__device__ __align__(16) float g_x[2][NN * DD];
__device__ __align__(16) __nv_bfloat16 g_xb[NN * DD];       // bf16 mirror of current x
__device__ __align__(16) __nv_bfloat16 g_xp[NN * 96];       // padded input x (bf16)
__device__ __align__(16) __nv_bfloat16 g_e[NE * DD];        // edge embeddings (bf16)
__device__ __align__(16) __nv_bfloat16 g_eap[NE * 64];      // padded edge attrs (bf16)
__device__ __align__(16) __nv_bfloat16 g_Wnp[128 * 96];     // Wn packed n-major [n][k] (pad 96)
__device__ __align__(16) __nv_bfloat16 g_Wep[128 * 64];     // We packed n-major [n][k]
__device__ __align__(16) __nv_bfloat16 g_Wcn[512 * 128];    // node W bf16 n-major, interleaved f/s
__device__ __align__(16) __nv_bfloat16 g_Wce[256 * 128];    // edge W bf16 n-major, interleaved f/s
__device__ __align__(16) __nv_bfloat16 g_ABnh[NN * 512];    // bf16 interleaved [AF0,AS0,...|BF0,BS0,...]
__device__ __align__(16) float g_msg[NN * DD];
__device__ __align__(16) float g_pooled[NG * DD];
__device__ __align__(16) float g_y[NG * DD];
__device__ __align__(16) float g_t1[NG * 64];
__device__ __align__(16) float g_t2[NG * 32];
__device__ __align__(16) float g_t3[NG * 16];
__device__ __align__(16) float g_bcat_e[256];               // interleaved edge bias (f32)
__device__ __align__(16) float g_bn[512];

// ---------------- math helpers ----------------
__device__ __forceinline__ float fsp(float v) {
    return (v > 20.0f) ? v : __logf(1.0f + __expf(v));
}
__device__ __forceinline__ float fsig(float v) {
    return __fdividef(1.0f, 1.0f + __expf(-v));
}
__device__ __forceinline__ void mma_bf16(float c[4], const uint32_t a[4], const uint32_t b[2]) {
    asm volatile(
        "mma.sync.aligned.m16n8k16.row.col.f32.bf16.bf16.f32 "
        "{%0,%1,%2,%3}, {%4,%5,%6,%7}, {%8,%9}, {%0,%1,%2,%3};"
        : "+f"(c[0]), "+f"(c[1]), "+f"(c[2]), "+f"(c[3])
        : "r"(a[0]), "r"(a[1]), "r"(a[2]), "r"(a[3]), "r"(b[0]), "r"(b[1]));
}

// bf16 fragment compute over current 32-k smem chunk using ldmatrix.
// A frag x4: lanes 0-15 -> rows (lane&15) @ kk, lanes 16-31 -> same rows @ kk+8.
// B frag x4 per fn-pair: grp=lane>>3: rows fp*16 + (grp>>1)*8 + (lane&7) @ kk + (grp&1)*8.
#define BMMA_CHUNK(Asrc, Bsrc)                                                          \
    do {                                                                                \
        _Pragma("unroll")                                                               \
        for (int ks = 0; ks < 2; ks++) {                                                \
            int kk = ks << 4;                                                           \
            uint32_t a[2][4], b[8][2];                                                  \
            _Pragma("unroll")                                                           \
            for (int fm = 0; fm < 2; fm++) {                                            \
                int row = warp_m * 32 + fm * 16 + (lane & 15);                          \
                uint32_t ad = (uint32_t)__cvta_generic_to_shared(                       \
                    &(Asrc)[row * BSTR + kk + ((lane >> 4) << 3)]);                     \
                asm volatile(                                                           \
                    "ldmatrix.sync.aligned.m8n8.x4.shared.b16 {%0,%1,%2,%3}, [%4];"     \
                    : "=r"(a[fm][0]), "=r"(a[fm][1]), "=r"(a[fm][2]), "=r"(a[fm][3])    \
                    : "r"(ad));                                                         \
            }                                                                           \
            _Pragma("unroll")                                                           \
            for (int fp = 0; fp < 4; fp++) {                                            \
                int grp = lane >> 3;                                                    \
                int row = warp_n * 64 + fp * 16 + ((grp >> 1) << 3) + (lane & 7);       \
                uint32_t bd = (uint32_t)__cvta_generic_to_shared(                       \
                    &(Bsrc)[row * BSTR + kk + ((grp & 1) << 3)]);                       \
                asm volatile(                                                           \
                    "ldmatrix.sync.aligned.m8n8.x4.shared.b16 {%0,%1,%2,%3}, [%4];"     \
                    : "=r"(b[fp * 2][0]), "=r"(b[fp * 2][1]),                           \
                      "=r"(b[fp * 2 + 1][0]), "=r"(b[fp * 2 + 1][1])                    \
                    : "r"(bd));                                                         \
            }                                                                           \
            _Pragma("unroll")                                                           \
            for (int fm = 0; fm < 2; fm++)                                              \
                _Pragma("unroll")                                                       \
                for (int fn = 0; fn < 8; fn++) mma_bf16(c[fm][fn], a[fm], b[fn]);       \
        }                                                                               \
    } while (0)

// ---------------- unified bf16 GEMM ----------------
// C = act(A[M,K]_bf16 @ Wn[Ncols,K]_bf16^T + bias)
// out_bf16=1: C is bf16. out_bf16=0: C is f32; if mirror != null also write bf16 mirror.
// grid (Ncols/128, ceil(M/128)); K % 32 == 0.
__global__ __launch_bounds__(256) void bf16_gemm(
    const __nv_bfloat16* __restrict__ A, const __nv_bfloat16* __restrict__ Wn,
    const float* __restrict__ bias, void* __restrict__ Cv,
    __nv_bfloat16* __restrict__ mirror,
    int M, int K, int Ncols, int act, int out_bf16)
{
    __shared__ __align__(16) __nv_bfloat16 As[2][128 * BSTR];
    __shared__ __align__(16) __nv_bfloat16 Bs[2][128 * BSTR];
    const int tid = threadIdx.x;
    const int lane = tid & 31, wid = tid >> 5;
    const int warp_m = wid & 3, warp_n = wid >> 2;
    const int row0 = blockIdx.y * 128;
    const int col0 = blockIdx.x * 128;
    const int mr = lane >> 2, kc = lane & 3;
    const int lr = tid >> 2, lq = (tid & 3) << 3;
    const int nch = K >> 5;

    float c[2][8][4];
#pragma unroll
    for (int i = 0; i < 2; i++)
#pragma unroll
        for (int j = 0; j < 8; j++)
#pragma unroll
            for (int q = 0; q < 4; q++) c[i][j][q] = 0.0f;

    uint4 pa[2], pb[2];
#pragma unroll
    for (int i = 0; i < 2; i++) {
        int r = lr + i * 64;
        int gr = row0 + r;
        pa[i] = (gr < M) ? *(const uint4*)(A + (size_t)gr * K + lq)
                         : make_uint4(0u, 0u, 0u, 0u);
        pb[i] = *(const uint4*)(Wn + (size_t)(col0 + r) * K + lq);
    }
#pragma unroll
    for (int i = 0; i < 2; i++) {
        int r = lr + i * 64;
        *(uint4*)&As[0][r * BSTR + lq] = pa[i];
        *(uint4*)&Bs[0][r * BSTR + lq] = pb[i];
    }
    for (int ch = 0; ch < nch; ch++) {
        int buf = ch & 1;
        if (ch + 1 < nch) {
            int k0 = (ch + 1) << 5;
#pragma unroll
            for (int i = 0; i < 2; i++) {
                int r = lr + i * 64;
                int gr = row0 + r;
                pa[i] = (gr < M) ? *(const uint4*)(A + (size_t)gr * K + k0 + lq)
                                 : make_uint4(0u, 0u, 0u, 0u);
                pb[i] = *(const uint4*)(Wn + (size_t)(col0 + r) * K + k0 + lq);
            }
        }
        __syncthreads();
        BMMA_CHUNK(As[buf], Bs[buf]);
        if (ch + 1 < nch) {
#pragma unroll
            for (int i = 0; i < 2; i++) {
                int r = lr + i * 64;
                *(uint4*)&As[buf ^ 1][r * BSTR + lq] = pa[i];
                *(uint4*)&Bs[buf ^ 1][r * BSTR + lq] = pb[i];
            }
        }
    }

#pragma unroll
    for (int fm = 0; fm < 2; fm++) {
        int rr = row0 + warp_m * 32 + fm * 16 + mr;
#pragma unroll
        for (int fn = 0; fn < 8; fn++) {
            int cc = col0 + warp_n * 64 + fn * 8 + kc * 2;
            float b0 = 0.0f, b1 = 0.0f;
            if (bias) { b0 = bias[cc]; b1 = bias[cc + 1]; }
            float v0 = c[fm][fn][0] + b0, v1 = c[fm][fn][1] + b1;
            float v2 = c[fm][fn][2] + b0, v3 = c[fm][fn][3] + b1;
            if (act) {
                v0 = fmaxf(v0, 0.0f); v1 = fmaxf(v1, 0.0f);
                v2 = fmaxf(v2, 0.0f); v3 = fmaxf(v3, 0.0f);
            }
            if (out_bf16) {
                __nv_bfloat16* C = (__nv_bfloat16*)Cv;
                if (rr < M)
                    *(__nv_bfloat162*)&C[(size_t)rr * Ncols + cc] = __floats2bfloat162_rn(v0, v1);
                if (rr + 8 < M)
                    *(__nv_bfloat162*)&C[(size_t)(rr + 8) * Ncols + cc] = __floats2bfloat162_rn(v2, v3);
            } else {
                float* C = (float*)Cv;
                if (rr < M) {
                    *(float2*)&C[(size_t)rr * Ncols + cc] = make_float2(v0, v1);
                    if (mirror)
                        *(__nv_bfloat162*)&mirror[(size_t)rr * Ncols + cc] = __floats2bfloat162_rn(v0, v1);
                }
                if (rr + 8 < M) {
                    *(float2*)&C[(size_t)(rr + 8) * Ncols + cc] = make_float2(v2, v3);
                    if (mirror)
                        *(__nv_bfloat162*)&mirror[(size_t)(rr + 8) * Ncols + cc] = __floats2bfloat162_rn(v2, v3);
                }
            }
        }
    }
}

// ---------------- fused bf16 edge GEMM + gating + scatter ----------------
// A = g_e [NE,128] bf16, W = g_Wce [256,128] bf16 n-major. grid (2, NE/128).
// Gathers node terms from bf16 g_ABnh (one 4B load per (f,s) pair).
__global__ __launch_bounds__(256) void edge_fused(const int* __restrict__ src,
                                                  const int* __restrict__ tgt)
{
    __shared__ __align__(16) __nv_bfloat16 As[2][128 * BSTR];
    __shared__ __align__(16) __nv_bfloat16 Bs[2][128 * BSTR];
    const int tid = threadIdx.x;
    const int lane = tid & 31, wid = tid >> 5;
    const int warp_m = wid & 3, warp_n = wid >> 2;
    const int row0 = blockIdx.y * 128;
    const int col0 = blockIdx.x * 128;
    const int mr = lane >> 2, kc = lane & 3;
    const int lr = tid >> 2, lq = (tid & 3) << 3;

    int ebase = row0 + warp_m * 32 + mr;
    int s0 = src[ebase], t0 = tgt[ebase];
    int s1 = src[ebase + 8], t1 = tgt[ebase + 8];
    int s2 = src[ebase + 16], t2 = tgt[ebase + 16];
    int s3 = src[ebase + 24], t3 = tgt[ebase + 24];

    float c[2][8][4];
#pragma unroll
    for (int i = 0; i < 2; i++)
#pragma unroll
        for (int j = 0; j < 8; j++)
#pragma unroll
            for (int q = 0; q < 4; q++) c[i][j][q] = 0.0f;

    uint4 pa[2], pb[2];
#pragma unroll
    for (int i = 0; i < 2; i++) {
        int r = lr + i * 64;
        pa[i] = *(const uint4*)(g_e + (size_t)(row0 + r) * 128 + lq);
        pb[i] = *(const uint4*)(g_Wce + (size_t)(col0 + r) * 128 + lq);
    }
#pragma unroll
    for (int i = 0; i < 2; i++) {
        int r = lr + i * 64;
        *(uint4*)&As[0][r * BSTR + lq] = pa[i];
        *(uint4*)&Bs[0][r * BSTR + lq] = pb[i];
    }
#pragma unroll 1
    for (int ch = 0; ch < 4; ch++) {
        int buf = ch & 1;
        if (ch + 1 < 4) {
            int k0 = (ch + 1) << 5;
#pragma unroll
            for (int i = 0; i < 2; i++) {
                int r = lr + i * 64;
                pa[i] = *(const uint4*)(g_e + (size_t)(row0 + r) * 128 + k0 + lq);
                pb[i] = *(const uint4*)(g_Wce + (size_t)(col0 + r) * 128 + k0 + lq);
            }
        }
        __syncthreads();
        BMMA_CHUNK(As[buf], Bs[buf]);
        if (ch + 1 < 4) {
#pragma unroll
            for (int i = 0; i < 2; i++) {
                int r = lr + i * 64;
                *(uint4*)&As[buf ^ 1][r * BSTR + lq] = pa[i];
                *(uint4*)&Bs[buf ^ 1][r * BSTR + lq] = pb[i];
            }
        }
    }

    int ss[4] = {s0, s1, s2, s3};
    int tt[4] = {t0, t1, t2, t3};
#pragma unroll
    for (int fm = 0; fm < 2; fm++) {
        int i1 = fm * 2, i2 = fm * 2 + 1;
        const __nv_bfloat162* sa1 = (const __nv_bfloat162*)(g_ABnh + (size_t)ss[i1] * 512);
        const __nv_bfloat162* ta1 = (const __nv_bfloat162*)(g_ABnh + (size_t)tt[i1] * 512 + 256);
        const __nv_bfloat162* sa2 = (const __nv_bfloat162*)(g_ABnh + (size_t)ss[i2] * 512);
        const __nv_bfloat162* ta2 = (const __nv_bfloat162*)(g_ABnh + (size_t)tt[i2] * 512 + 256);
        float* m1 = g_msg + (size_t)ss[i1] * DD;
        float* m2 = g_msg + (size_t)ss[i2] * DD;
#pragma unroll
        for (int fn = 0; fn < 8; fn++) {
            int cc = col0 + warp_n * 64 + fn * 8 + kc * 2;
            int d = cc >> 1;
            float2 bi = *(const float2*)&g_bcat_e[cc];
            float2 u1 = __bfloat1622float2(sa1[d]);
            float2 v1 = __bfloat1622float2(ta1[d]);
            float f1 = c[fm][fn][0] + bi.x + u1.x + v1.x;
            float w1 = c[fm][fn][1] + bi.y + u1.y + v1.y;
            atomicAdd(&m1[d], fsig(f1) * fsp(w1));
            float2 u2 = __bfloat1622float2(sa2[d]);
            float2 v2 = __bfloat1622float2(ta2[d]);
            float f2 = c[fm][fn][2] + bi.x + u2.x + v2.x;
            float w2 = c[fm][fn][3] + bi.y + u2.y + v2.y;
            atomicAdd(&m2[d], fsig(f2) * fsp(w2));
        }
    }
}

// ---------------- small kernels ----------------
__global__ void zero_kernel(float* p, int n) {
    int i = blockIdx.x * blockDim.x + threadIdx.x;
    if (i < n) p[i] = 0.0f;
}

// vectorized pads: 8 bf16 per thread (uint4 store)
__global__ void pad_x(const float* __restrict__ x) {
    int idx = blockIdx.x * blockDim.x + threadIdx.x;
    if (idx >= NN * 12) return;
    int r = idx / 12, kb = (idx - r * 12) << 3;
    __nv_bfloat16 v[8];
#pragma unroll
    for (int j = 0; j < 8; j++) {
        int k = kb + j;
        v[j] = __float2bfloat16(k < 92 ? x[r * 92 + k] : 0.0f);
    }
    *(uint4*)&g_xp[(size_t)r * 96 + kb] = *(uint4*)v;
}

__global__ void pack_Wn(const float* __restrict__ Wn) {
    int idx = blockIdx.x * blockDim.x + threadIdx.x;
    if (idx >= 128 * 96) return;
    int n = idx / 96, k = idx - n * 96;
    g_Wnp[idx] = __float2bfloat16(k < 92 ? Wn[k * 128 + n] : 0.0f);
}

__global__ void pad_ea(const float* __restrict__ ea) {
    int idx = blockIdx.x * blockDim.x + threadIdx.x;
    if (idx >= NE * 8) return;
    int e = idx >> 3, kb = (idx & 7) << 3;
    __nv_bfloat16 v[8];
#pragma unroll
    for (int j = 0; j < 8; j++) {
        int k = kb + j;
        v[j] = __float2bfloat16(k < 41 ? ea[(size_t)e * 41 + k] : 0.0f);
    }
    *(uint4*)&g_eap[(size_t)e * 64 + kb] = *(uint4*)v;
}

__global__ void pack_We(const float* __restrict__ We) {
    int idx = blockIdx.x * blockDim.x + threadIdx.x;
    if (idx >= 128 * 64) return;
    int n = idx >> 6, k = idx & 63;
    g_Wep[idx] = __float2bfloat16(k < 41 ? We[k * 128 + n] : 0.0f);
}

// node weights -> bf16 n-major [512 n][128 k], n interleaved f/s; n<256 top block, else mid block
__global__ void pack_node(const float* __restrict__ Wf, const float* __restrict__ Ws) {
    int idx = blockIdx.x * blockDim.x + threadIdx.x;
    if (idx >= 512 * 128) return;
    int n = idx >> 7, k = idx & 127;
    float v;
    if (n < 256) {
        int d = n >> 1;
        v = (n & 1) ? Ws[k * 128 + d] : Wf[k * 128 + d];
    } else {
        int d = (n - 256) >> 1;
        v = (n & 1) ? Ws[(128 + k) * 128 + d] : Wf[(128 + k) * 128 + d];
    }
    g_Wcn[idx] = __float2bfloat16(v);
}

__global__ void pack_edge(const float* __restrict__ Wf, const float* __restrict__ Ws,
                          const float* __restrict__ bf, const float* __restrict__ bs) {
    int idx = blockIdx.x * blockDim.x + threadIdx.x;
    if (idx >= 256 * 128) return;
    int n = idx >> 7, k = idx & 127;
    int d = n >> 1;
    float v = (n & 1) ? Ws[(256 + k) * 128 + d] : Wf[(256 + k) * 128 + d];
    g_Wce[idx] = __float2bfloat16(v);
    if (idx < 256) g_bcat_e[idx] = (idx & 1) ? bs[idx >> 1] : bf[idx >> 1];
}

__global__ void bn_stats() {
    int d = threadIdx.x;
    float s = 0.0f, ss = 0.0f;
    for (int r = blockIdx.x; r < NN; r += gridDim.x) {
        float v = g_msg[(size_t)r * DD + d];
        s += v; ss += v * v;
    }
    atomicAdd(&g_bn[d], s);
    atomicAdd(&g_bn[128 + d], ss);
}

__global__ void bn_finalize(const float* __restrict__ gamma, const float* __restrict__ beta) {
    int d = threadIdx.x;
    float mu  = g_bn[d] * (1.0f / NN);
    float var = g_bn[128 + d] * (1.0f / NN) - mu * mu;
    float rstd = rsqrtf(var + 1e-5f);
    float sc = rstd * gamma[d];
    g_bn[256 + d] = sc;
    g_bn[384 + d] = beta[d] - mu * sc;
}

// also zeroes msg after reading (removes per-layer zero_kernel; invariant: msg==0 at call end)
__global__ __launch_bounds__(128) void node_update(const int* __restrict__ batch, int cur) {
    int d = threadIdx.x;
    int r0 = blockIdx.x * 32;
    int rend = min(r0 + 32, NN);
    const float* xin = g_x[cur];
    float* xout = g_x[cur ^ 1];
    float sc = g_bn[256 + d], sh = g_bn[384 + d];
    float acc = 0.0f;
    int curb = batch[r0];
    for (int r = r0; r < rend; r++) {
        int b = batch[r];
        if (b != curb) {
            atomicAdd(&g_pooled[(size_t)curb * DD + d], acc);
            acc = 0.0f; curb = b;
        }
        size_t idx = (size_t)r * DD + d;
        float m = g_msg[idx];
        g_msg[idx] = 0.0f;
        float v = fsp(xin[idx] + m * sc + sh);
        xout[idx] = v;
        g_xb[idx] = __float2bfloat16(v);
        acc += v;
    }
    atomicAdd(&g_pooled[(size_t)curb * DD + d], acc);
}

__global__ void small_gemm(const float* __restrict__ A, const float* __restrict__ W,
                           const float* __restrict__ b, float* __restrict__ C,
                           int M, int K, int Nc, int accum, int act) {
    int idx = blockIdx.x * blockDim.x + threadIdx.x;
    if (idx >= M * Nc) return;
    int r = idx / Nc, c = idx % Nc;
    float s = b[c];
    for (int k = 0; k < K; k++) s = fmaf(A[r * K + k], W[k * Nc + c], s);
    if (accum) s += C[idx];
    if (act) s = fmaxf(s, 0.0f);
    C[idx] = s;
}

// ---------------- host ----------------
static float* symaddr(const void* sym) {
    void* p = nullptr;
    cudaGetSymbolAddress(&p, sym);
    return (float*)p;
}

extern "C" void kernel_launch(void* const* d_in, const int* in_sizes, int n_in,
                              void* d_out, int out_size)
{
    const float* x_in = (const float*)d_in[0];
    const float* ea   = (const float*)d_in[1];
    const int*   esrc = (const int*)d_in[2];
    const int*   etgt = (const int*)d_in[3];
    const int*   nbat = (const int*)d_in[4];
    const float* Wn   = (const float*)d_in[5];
    const float* bne  = (const float*)d_in[6];
    const float* We   = (const float*)d_in[7];
    const float* bee  = (const float*)d_in[8];
    const float* Wf   = (const float*)d_in[9];
    const float* bf   = (const float*)d_in[10];
    const float* Ws   = (const float*)d_in[11];
    const float* bs   = (const float*)d_in[12];
    int iWg = 15, ibg = 16, iga = 13, ibe = 14;
    if (in_sizes[13] == 5 * 128 * 128) { iWg = 13; ibg = 14; iga = 15; ibe = 16; }
    const float* Wg    = (const float*)d_in[iWg];
    const float* bg    = (const float*)d_in[ibg];
    const float* gamma = (const float*)d_in[iga];
    const float* beta  = (const float*)d_in[ibe];
    const float* Wr1 = (const float*)d_in[17]; const float* br1 = (const float*)d_in[18];
    const float* Wr2 = (const float*)d_in[19]; const float* br2 = (const float*)d_in[20];
    const float* Wr3 = (const float*)d_in[21]; const float* br3 = (const float*)d_in[22];
    const float* Wr4 = (const float*)d_in[23]; const float* br4 = (const float*)d_in[24];
    float* out = (float*)d_out;

    float* xbuf   = symaddr(g_x);
    float* msg    = symaddr(g_msg);
    float* pooled = symaddr(g_pooled);
    float* ybuf   = symaddr(g_y);
    float* t1     = symaddr(g_t1);
    float* t2     = symaddr(g_t2);
    float* t3     = symaddr(g_t3);
    float* bnb    = symaddr(g_bn);
    __nv_bfloat16* xb   = (__nv_bfloat16*)symaddr(g_xb);
    __nv_bfloat16* xp   = (__nv_bfloat16*)symaddr(g_xp);
    __nv_bfloat16* ebuf = (__nv_bfloat16*)symaddr(g_e);
    __nv_bfloat16* eap  = (__nv_bfloat16*)symaddr(g_eap);
    __nv_bfloat16* wnp  = (__nv_bfloat16*)symaddr(g_Wnp);
    __nv_bfloat16* wep  = (__nv_bfloat16*)symaddr(g_Wep);
    __nv_bfloat16* wcn  = (__nv_bfloat16*)symaddr(g_Wcn);
    __nv_bfloat16* abnh = (__nv_bfloat16*)symaddr(g_ABnh);

    // embeddings (all bf16 tensor-core)
    pad_x<<<(NN * 12 + 255) / 256, 256>>>(x_in);
    pack_Wn<<<(128 * 96 + 255) / 256, 256>>>(Wn);
    bf16_gemm<<<dim3(1, (NN + 127) / 128), 256>>>(xp, wnp, bne, xbuf, xb, NN, 96, 128, 1, 0);
    pad_ea<<<(NE * 8 + 255) / 256, 256>>>(ea);
    pack_We<<<(128 * 64 + 255) / 256, 256>>>(We);
    bf16_gemm<<<dim3(1, NE / 128), 256>>>(eap, wep, bee, ebuf, nullptr, NE, 64, 128, 1, 1);
    zero_kernel<<<(NG * DD + 255) / 256, 256>>>(ybuf, NG * DD);
    zero_kernel<<<(NN * DD + 255) / 256, 256>>>(msg, NN * DD);  // layer-0 safety (no-op after first call)

    int cur = 0;
    for (int i = 0; i < 5; i++) {
        const float* Wfi = Wf + (size_t)i * 384 * 128;
        const float* Wsi = Ws + (size_t)i * 384 * 128;
        pack_node<<<(512 * 128 + 255) / 256, 256>>>(Wfi, Wsi);
        pack_edge<<<(256 * 128 + 255) / 256, 256>>>(Wfi, Wsi, bf + i * 128, bs + i * 128);

        // node GEMM -> bf16 ABn
        bf16_gemm<<<dim3(4, (NN + 127) / 128), 256>>>(
            xb, wcn, nullptr, abnh, nullptr, NN, 128, 512, 0, 1);

        edge_fused<<<dim3(2, NE / 128), 256>>>(esrc, etgt);

        zero_kernel<<<1, 256>>>(bnb, 256);
        bn_stats<<<512, 128>>>();
        bn_finalize<<<1, 128>>>(gamma + i * 128, beta + i * 128);

        zero_kernel<<<(NG * DD + 255) / 256, 256>>>(pooled, NG * DD);
        node_update<<<(NN + 31) / 32, 128>>>(nbat, cur);

        small_gemm<<<(NG * 128 + 255) / 256, 256>>>(pooled, Wg + (size_t)i * 128 * 128,
                                                    bg + i * 128, ybuf, NG, 128, 128, 1, 0);
        cur ^= 1;
    }

    small_gemm<<<(NG * 64 + 255) / 256, 256>>>(ybuf, Wr1, br1, t1, NG, 128, 64, 0, 1);
    small_gemm<<<(NG * 32 + 255) / 256, 256>>>(t1, Wr2, br2, t2, NG, 64, 32, 0, 1);
    small_gemm<<<(NG * 16 + 255) / 256, 256>>>(t2, Wr3, br3, t3, NG, 32, 16, 0, 1);
    small_gemm<<<(NG * 1 + 255) / 256, 256>>>(t3, Wr4, br4, out, NG, 16, 1, 0, 1);
}